// round 1
// baseline (speedup 1.0000x reference)
#include <cuda_runtime.h>
#include <math.h>

#define KNB 30
#define PAD 132
#define EVPAD 260

typedef unsigned long long u64;

__device__ __forceinline__ u64 fma2(u64 a, u64 b, u64 c){
  u64 d; asm("fma.rn.f32x2 %0, %1, %2, %3;" : "=l"(d) : "l"(a), "l"(b), "l"(c)); return d;
}
__device__ __forceinline__ u64 bcast2(float v){
  u64 d; asm("mov.b64 %0, {%1, %1};" : "=l"(d) : "f"(v)); return d;
}
__device__ __forceinline__ float2 unpack2(u64 v){
  float2 r; asm("mov.b64 {%0, %1}, %2;" : "=f"(r.x), "=f"(r.y) : "l"(v)); return r;
}

// Transpose a 128-col chunk of weight matrix W[h][coff+c] into wb[c*PAD+h].
// Lanes map to consecutive h -> conflict-free smem writes.
__device__ __forceinline__ void load_wT(const float* __restrict__ W, float* __restrict__ wb,
                                        int tid, int rowstride, int coff){
  #pragma unroll
  for (int i = tid; i < 128*32; i += 256){
    int h  = i & 127;
    int c4 = (i >> 7) << 2;
    float4 w = *(const float4*)(W + (size_t)h*rowstride + coff + c4);
    wb[(c4+0)*PAD + h] = w.x;
    wb[(c4+1)*PAD + h] = w.y;
    wb[(c4+2)*PAD + h] = w.z;
    wb[(c4+3)*PAD + h] = w.w;
  }
}

// acc[j] accumulates output channels (h0+2j, h0+2j+1) packed as f32x2,
// reducing over 128 c's. arow = activation row (float4-aligned).
__device__ __forceinline__ void proj128(const float* __restrict__ arow,
                                        const float* __restrict__ wb,
                                        u64 acc[8], int h0){
  #pragma unroll 2
  for (int c = 0; c < 128; c += 4){
    float4 a = *(const float4*)(arow + c);
    #pragma unroll
    for (int cc = 0; cc < 4; cc++){
      float av = (cc==0)?a.x:(cc==1)?a.y:(cc==2)?a.z:a.w;
      u64 a2 = bcast2(av);
      const u64* wr = (const u64*)(wb + (c+cc)*PAD + h0);
      #pragma unroll
      for (int j = 0; j < 8; j++) acc[j] = fma2(a2, wr[j], acc[j]);
    }
  }
}

__global__ void __launch_bounds__(256, 1) na_kernel(
  const float* __restrict__ hV,  const float* __restrict__ hEV,
  const float* __restrict__ hKV, const float* __restrict__ hKE,
  const float* __restrict__ maskA,
  const float* __restrict__ WQ,  const float* __restrict__ WK1,
  const float* __restrict__ WK2, const float* __restrict__ WV,
  const float* __restrict__ WO,  float* __restrict__ out)
{
  extern __shared__ float smem[];
  float* wbuf = smem;               // 128*132 = 16896 floats (reused per stage)
  float* rgn  = smem + 16896;       // 11880-float union region
  float* inb  = rgn;                // 30*132  (h_KE then h_KV)
  float* k1b  = rgn + 3960;         // 30*132
  float* k2b  = rgn + 7920;         // 30*132
  float* evb  = rgn;                // 30*260  (aliases inb+k1b after softmax)
  float* vb   = rgn + 7800;         // 30*132  (aliases k1b tail + k2b)
  float* sQ   = smem + 28776;       // 128
  float* sHU  = sQ + 128;           // 128
  float* sAttn= sHU + 128;          // 128
  float* sQx  = sAttn + 128;        // 128   (total 29288 floats = 117152 B)

  const int tid = threadIdx.x;
  const int bn  = blockIdx.x;
  const int k   = tid & 31;
  const int h0  = (tid >> 5) * 16;
  const int keff = (k < KNB) ? k : 0;

  // ---- phase 0: load h_V row, h_KE tile, W_K1^T ----
  if (tid < 32)
    *(float4*)(sQx + tid*4) = *(const float4*)(hV + (size_t)bn*128 + tid*4);
  {
    const float* src = hKE + (size_t)bn*3840;
    for (int i = tid*4; i < 3840; i += 1024){
      int kk = i >> 7, c = i & 127;
      *(float4*)(inb + kk*PAD + c) = *(const float4*)(src + i);
    }
  }
  load_wT(WK1, wbuf, tid, 128, 0);
  __syncthreads();

  // ---- K1 = h_KE @ W_K1^T ----
  u64 acc[8];
  #pragma unroll
  for (int j = 0; j < 8; j++) acc[j] = 0ull;
  proj128(inb + keff*PAD, wbuf, acc, h0);
  if (k < KNB){
    #pragma unroll
    for (int j = 0; j < 8; j++) *(float2*)(k1b + k*PAD + h0 + 2*j) = unpack2(acc[j]);
  }
  __syncthreads();

  // ---- phase 1: h_KV tile + W_K2^T ----
  {
    const float* src = hKV + (size_t)bn*3840;
    for (int i = tid*4; i < 3840; i += 1024){
      int kk = i >> 7, c = i & 127;
      *(float4*)(inb + kk*PAD + c) = *(const float4*)(src + i);
    }
  }
  load_wT(WK2, wbuf, tid, 128, 0);
  __syncthreads();

  // ---- K2 = h_KV @ W_K2^T ----
  #pragma unroll
  for (int j = 0; j < 8; j++) acc[j] = 0ull;
  proj128(inb + keff*PAD, wbuf, acc, h0);
  if (k < KNB){
    #pragma unroll
    for (int j = 0; j < 8; j++) *(float2*)(k2b + k*PAD + h0 + 2*j) = unpack2(acc[j]);
  }

  // ---- Q = h_V @ W_Q^T (tiny, direct from gmem, L1-resident) ----
  if (tid < 128){
    float qa = 0.f;
    const float4* wq = (const float4*)(WQ + (size_t)tid*128);
    #pragma unroll 8
    for (int j = 0; j < 32; j++){
      float4 w = wq[j];
      float4 x = *(const float4*)(sQx + 4*j);
      qa += w.x*x.x + w.y*x.y + w.z*x.z + w.w*x.w;
    }
    sQ[tid] = qa;
  }
  __syncthreads();

  // ---- trilinear logits + masked softmax (warp per head) ----
  if (tid < 128){
    int kk = tid & 31, head = tid >> 5;
    bool valid = kk < KNB;
    int hh = head*32;
    float lg = -3.402823466e38f, m = 0.f;
    if (valid){
      float a = 0.f;
      const float4* q4 = (const float4*)(sQ  + hh);
      const float4* x4 = (const float4*)(k1b + kk*PAD + hh);
      const float4* y4 = (const float4*)(k2b + kk*PAD + hh);
      #pragma unroll
      for (int j = 0; j < 8; j++){
        float4 q = q4[j], x = x4[j], y = y4[j];
        a += q.x*x.x*y.x + q.y*x.y*y.y + q.z*x.z*y.z + q.w*x.w*y.w;
      }
      m = maskA[(size_t)bn*KNB + kk];
      lg = (m > 0.f) ? a * (1.f/32.f) : -3.402823466e38f;
    }
    float mx = lg;
    #pragma unroll
    for (int o = 16; o; o >>= 1) mx = fmaxf(mx, __shfl_xor_sync(0xffffffffu, mx, o));
    float e = valid ? expf(lg - mx) : 0.f;
    float s = e;
    #pragma unroll
    for (int o = 16; o; o >>= 1) s += __shfl_xor_sync(0xffffffffu, s, o);
    sAttn[tid] = valid ? e * m / s : 0.f;
  }
  __syncthreads();   // k1b/k2b dead from here; evb/vb may alias them

  // ---- V = h_EV @ W_V^T  (C=256, two 128-c chunks through wbuf) ----
  {
    const float* src = hEV + (size_t)bn*7680;
    for (int i = tid*4; i < 7680; i += 1024){
      int kk = i >> 8, c = i & 255;
      *(float4*)(evb + kk*EVPAD + c) = *(const float4*)(src + i);
    }
  }
  load_wT(WV, wbuf, tid, 256, 0);
  __syncthreads();
  #pragma unroll
  for (int j = 0; j < 8; j++) acc[j] = 0ull;
  proj128(evb + keff*EVPAD, wbuf, acc, h0);
  __syncthreads();
  load_wT(WV, wbuf, tid, 256, 128);
  __syncthreads();
  proj128(evb + keff*EVPAD + 128, wbuf, acc, h0);
  if (k < KNB){
    #pragma unroll
    for (int j = 0; j < 8; j++) *(float2*)(vb + k*PAD + h0 + 2*j) = unpack2(acc[j]);
  }
  __syncthreads();

  // ---- aggregate over neighbors ----
  if (tid < 128){
    int head = tid >> 5;
    float a = 0.f;
    #pragma unroll
    for (int kk = 0; kk < KNB; kk++)
      a += sAttn[head*32 + kk] * vb[kk*PAD + tid];
    sHU[tid] = a;
  }
  __syncthreads();

  // ---- out = h_upd @ W_O^T ----
  if (tid < 128){
    float a = 0.f;
    const float4* wo = (const float4*)(WO + (size_t)tid*128);
    #pragma unroll 8
    for (int j = 0; j < 32; j++){
      float4 w = wo[j];
      float4 x = *(const float4*)(sHU + 4*j);
      a += w.x*x.x + w.y*x.y + w.z*x.z + w.w*x.w;
    }
    out[(size_t)bn*128 + tid] = a;
  }
}

extern "C" void kernel_launch(void* const* d_in, const int* in_sizes, int n_in,
                              void* d_out, int out_size)
{
  const float* hV    = (const float*)d_in[0];
  const float* hEV   = (const float*)d_in[1];
  const float* hKV   = (const float*)d_in[2];
  const float* hKE   = (const float*)d_in[3];
  const float* maskA = (const float*)d_in[4];
  const float* WQ    = (const float*)d_in[5];
  const float* WK1   = (const float*)d_in[6];
  const float* WK2   = (const float*)d_in[7];
  const float* WV    = (const float*)d_in[8];
  const float* WO    = (const float*)d_in[9];
  float* out = (float*)d_out;

  const int smem_bytes = 29288 * 4;   // 117152 B
  cudaFuncSetAttribute(na_kernel, cudaFuncAttributeMaxDynamicSharedMemorySize, smem_bytes);
  na_kernel<<<8000, 256, smem_bytes>>>(hV, hEV, hKV, hKE, maskA, WQ, WK1, WK2, WV, WO, out);
}

// round 7
// speedup vs baseline: 1.7632x; 1.7632x over previous
#include <cuda_runtime.h>
#include <math.h>

#define KNB   30
#define TPC   2          // tokens per CTA
#define WSTR  128        // transposed-weight row stride (floats)
#define ASTR  65         // transposed-activation row stride (floats), odd -> conflict-free
#define NEGF  (-3.402823466e38f)

typedef unsigned long long u64;

__device__ __forceinline__ u64 fma2(u64 a, u64 b, u64 c){
  u64 d; asm("fma.rn.f32x2 %0, %1, %2, %3;" : "=l"(d) : "l"(a), "l"(b), "l"(c)); return d;
}
__device__ __forceinline__ u64 mul2(u64 a, u64 b){
  u64 d; asm("mul.rn.f32x2 %0, %1, %2;" : "=l"(d) : "l"(a), "l"(b)); return d;
}
__device__ __forceinline__ u64 bcast2(float v){
  u64 d; asm("mov.b64 %0, {%1, %1};" : "=l"(d) : "f"(v)); return d;
}
__device__ __forceinline__ float2 unpack2(u64 v){
  float2 r; asm("mov.b64 {%0, %1}, %2;" : "=f"(r.x), "=f"(r.y) : "l"(v)); return r;
}

// smem layout (floats)
#define OFF_W    0                      // 128*128 transposed weight
#define OFF_A    (OFF_W + 128*WSTR)     // 128*ASTR transposed activations (2 tokens)
#define OFF_QX   (OFF_A + 128*ASTR)     // 2*128 h_V rows
#define OFF_Q    (OFF_QX + 256)         // 2*128 Q
#define OFF_P    (OFF_Q + 256)          // 8 warps * 2 tok * 32 partial logits
#define OFF_ATT  (OFF_P + 512)          // 2*128 attn
#define OFF_HU   (OFF_ATT + 256)        // 2*128 h_upd
#define SMEM_FL  (OFF_HU + 256)

// Transpose 128-col chunk of W[h][coff+c] (row stride rs) into wb[c*WSTR+h].
__device__ __forceinline__ void load_wT(const float* __restrict__ W, float* __restrict__ wb,
                                        int tid, int rs, int coff){
  #pragma unroll
  for (int i = tid; i < 128*32; i += 256){
    int h  = i & 127;
    int c4 = (i >> 7) << 2;
    float4 w = *(const float4*)(W + (size_t)h*rs + coff + c4);
    wb[(c4+0)*WSTR + h] = w.x;
    wb[(c4+1)*WSTR + h] = w.y;
    wb[(c4+2)*WSTR + h] = w.z;
    wb[(c4+3)*WSTR + h] = w.w;
  }
}

// Load [30][128] activation block (cols coff..coff+127, row stride rs) of one token
// into aT[c*ASTR + slot + r]. Coalesced LDG.32, conflict-free STS.32.
__device__ __forceinline__ void load_aT(const float* __restrict__ src, float* __restrict__ aT,
                                        int tid, int rs, int coff, int slot){
  #pragma unroll
  for (int i = tid; i < KNB*128; i += 256){
    int r = i >> 7, c = i & 127;
    aT[c*ASTR + slot + r] = src[(size_t)r*rs + coff + c];
  }
}

// acc0/acc1: 8 packed f32x2 accumulators (16 channels h0..h0+15) for tokens 0/1.
__device__ __forceinline__ void proj(const float* __restrict__ aT, const float* __restrict__ wb,
                                     u64* __restrict__ acc0, u64* __restrict__ acc1,
                                     int h0, int lane){
  const float* ap = aT + lane;
  const float* wp = wb + h0;
  #pragma unroll 4
  for (int c = 0; c < 128; c++){
    ulonglong2 q0 = *(const ulonglong2*)(wp);
    ulonglong2 q1 = *(const ulonglong2*)(wp + 4);
    ulonglong2 q2 = *(const ulonglong2*)(wp + 8);
    ulonglong2 q3 = *(const ulonglong2*)(wp + 12);
    u64 a0 = bcast2(ap[0]);
    u64 a1 = bcast2(ap[32]);
    acc0[0] = fma2(a0, q0.x, acc0[0]);  acc0[1] = fma2(a0, q0.y, acc0[1]);
    acc0[2] = fma2(a0, q1.x, acc0[2]);  acc0[3] = fma2(a0, q1.y, acc0[3]);
    acc0[4] = fma2(a0, q2.x, acc0[4]);  acc0[5] = fma2(a0, q2.y, acc0[5]);
    acc0[6] = fma2(a0, q3.x, acc0[6]);  acc0[7] = fma2(a0, q3.y, acc0[7]);
    acc1[0] = fma2(a1, q0.x, acc1[0]);  acc1[1] = fma2(a1, q0.y, acc1[1]);
    acc1[2] = fma2(a1, q1.x, acc1[2]);  acc1[3] = fma2(a1, q1.y, acc1[3]);
    acc1[4] = fma2(a1, q2.x, acc1[4]);  acc1[5] = fma2(a1, q2.y, acc1[5]);
    acc1[6] = fma2(a1, q3.x, acc1[6]);  acc1[7] = fma2(a1, q3.y, acc1[7]);
    wp += WSTR; ap += ASTR;
  }
}

// 128-out dense layer: thread (t,ch) computes dot(wT[:,ch], x[t,:]).
__device__ __forceinline__ float dense128(const float* __restrict__ wb,
                                          const float* __restrict__ x, int ch){
  float s0=0.f, s1=0.f, s2=0.f, s3=0.f;
  const float* wp = wb + ch;
  #pragma unroll 8
  for (int c = 0; c < 128; c += 4){
    s0 += wp[(c+0)*WSTR] * x[c+0];
    s1 += wp[(c+1)*WSTR] * x[c+1];
    s2 += wp[(c+2)*WSTR] * x[c+2];
    s3 += wp[(c+3)*WSTR] * x[c+3];
  }
  return (s0+s1)+(s2+s3);
}

__global__ void __launch_bounds__(256, 1) na_kernel(
  const float* __restrict__ hV,  const float* __restrict__ hEV,
  const float* __restrict__ hKV, const float* __restrict__ hKE,
  const float* __restrict__ maskA,
  const float* __restrict__ WQ,  const float* __restrict__ WK1,
  const float* __restrict__ WK2, const float* __restrict__ WV,
  const float* __restrict__ WO,  float* __restrict__ out)
{
  extern __shared__ float smem[];
  float* wbuf = smem + OFF_W;
  float* aT   = smem + OFF_A;
  float* sQx  = smem + OFF_QX;
  float* sQ   = smem + OFF_Q;
  float* part = smem + OFF_P;
  float* attnS= smem + OFF_ATT;
  float* sHU  = smem + OFF_HU;

  const int tid  = threadIdx.x;
  const int lane = tid & 31;
  const int w    = tid >> 5;
  const int h0   = w * 16;
  const int bn   = blockIdx.x;          // covers tokens 2bn, 2bn+1
  const size_t tok0 = (size_t)(2*bn);

  // ---- stage 1: h_V rows, KE tile, W_K1^T; zero pad rows once ----
  sQx[tid] = hV[(tok0 + (tid>>7))*128 + (tid&127)];
  if (tid < 128){
    aT[tid*ASTR + 30] = 0.f; aT[tid*ASTR + 31] = 0.f;
    aT[tid*ASTR + 62] = 0.f; aT[tid*ASTR + 63] = 0.f;
  }
  load_aT(hKE + tok0*KNB*128,     aT, tid, 128, 0, 0);
  load_aT(hKE + (tok0+1)*KNB*128, aT, tid, 128, 0, 32);
  load_wT(WK1, wbuf, tid, 128, 0);
  __syncthreads();

  // ---- K1 ----
  u64 k1a[8], k1b[8];
  #pragma unroll
  for (int j = 0; j < 8; j++){ k1a[j]=0ull; k1b[j]=0ull; }
  proj(aT, wbuf, k1a, k1b, h0, lane);
  __syncthreads();

  // ---- stage 2: KV tile, W_K2^T ----
  load_aT(hKV + tok0*KNB*128,     aT, tid, 128, 0, 0);
  load_aT(hKV + (tok0+1)*KNB*128, aT, tid, 128, 0, 32);
  load_wT(WK2, wbuf, tid, 128, 0);
  __syncthreads();

  // ---- K2 ----
  u64 k2a[8], k2b[8];
  #pragma unroll
  for (int j = 0; j < 8; j++){ k2a[j]=0ull; k2b[j]=0ull; }
  proj(aT, wbuf, k2a, k2b, h0, lane);
  __syncthreads();

  // ---- stage 3: W_Q^T, then Q ----
  load_wT(WQ, wbuf, tid, 128, 0);
  __syncthreads();
  {
    int t = tid >> 7, ch = tid & 127;
    sQ[t*128 + ch] = dense128(wbuf, sQx + t*128, ch);
  }
  __syncthreads();

  // ---- trilinear partial logits: p[w][t][lane] = sum_{ch in warp} q*k1*k2 ----
  #pragma unroll
  for (int t = 0; t < TPC; t++){
    const u64* q2 = (const u64*)(sQ + t*128 + h0);
    u64* K1 = t ? k1b : k1a;
    u64* K2 = t ? k2b : k2a;
    u64 p2 = 0ull;
    #pragma unroll
    for (int j = 0; j < 8; j++) p2 = fma2(q2[j], mul2(K1[j], K2[j]), p2);
    float2 f = unpack2(p2);
    part[(w*2 + t)*32 + lane] = f.x + f.y;
  }
  __syncthreads();

  // ---- masked softmax: warp w -> (t = w>>2, head = w&3) ----
  {
    int t = w >> 2, h = w & 3;
    float m = 0.f, lg = NEGF;
    if (lane < KNB){
      float a = part[((2*h)*2 + t)*32 + lane] + part[((2*h+1)*2 + t)*32 + lane];
      m = maskA[(tok0 + t)*KNB + lane];
      lg = (m > 0.f) ? a * (1.f/32.f) : NEGF;
    }
    float mx = lg;
    #pragma unroll
    for (int o = 16; o; o >>= 1) mx = fmaxf(mx, __shfl_xor_sync(0xffffffffu, mx, o));
    float e = (lane < KNB) ? __expf(lg - mx) : 0.f;
    float s = e;
    #pragma unroll
    for (int o = 16; o; o >>= 1) s += __shfl_xor_sync(0xffffffffu, s, o);
    attnS[t*128 + h*32 + lane] = (lane < KNB) ? e * m / s : 0.f;
  }
  __syncthreads();

  // ---- V = h_EV @ W_V^T in two 128-col halves, accumulated in registers ----
  u64 va[8], vb[8];
  #pragma unroll
  for (int j = 0; j < 8; j++){ va[j]=0ull; vb[j]=0ull; }
  #pragma unroll
  for (int hf = 0; hf < 2; hf++){
    load_aT(hEV + tok0*KNB*256,     aT, tid, 256, hf*128, 0);
    load_aT(hEV + (tok0+1)*KNB*256, aT, tid, 256, hf*128, 32);
    load_wT(WV, wbuf, tid, 256, hf*128);
    __syncthreads();
    proj(aT, wbuf, va, vb, h0, lane);
    __syncthreads();
  }

  // ---- attention-weighted reduction over neighbors (lanes) ----
  {
    int head = w >> 1;
    #pragma unroll
    for (int t = 0; t < TPC; t++){
      float a = attnS[t*128 + head*32 + lane];
      u64* V = t ? vb : va;
      float vf[16];
      #pragma unroll
      for (int j = 0; j < 8; j++){
        float2 f = unpack2(V[j]);
        vf[2*j] = f.x * a; vf[2*j+1] = f.y * a;
      }
      #pragma unroll
      for (int j = 0; j < 16; j++){
        #pragma unroll
        for (int o = 16; o; o >>= 1) vf[j] += __shfl_xor_sync(0xffffffffu, vf[j], o);
      }
      if (lane == 0){
        #pragma unroll
        for (int j = 0; j < 16; j++) sHU[t*128 + h0 + j] = vf[j];
      }
    }
  }
  __syncthreads();

  // ---- output projection ----
  load_wT(WO, wbuf, tid, 128, 0);
  __syncthreads();
  {
    int t = tid >> 7, ch = tid & 127;
    out[(tok0 + t)*128 + ch] = dense128(wbuf, sHU + t*128, ch);
  }
}

extern "C" void kernel_launch(void* const* d_in, const int* in_sizes, int n_in,
                              void* d_out, int out_size)
{
  const float* hV    = (const float*)d_in[0];
  const float* hEV   = (const float*)d_in[1];
  const float* hKV   = (const float*)d_in[2];
  const float* hKE   = (const float*)d_in[3];
  const float* maskA = (const float*)d_in[4];
  const float* WQ    = (const float*)d_in[5];
  const float* WK1   = (const float*)d_in[6];
  const float* WK2   = (const float*)d_in[7];
  const float* WV    = (const float*)d_in[8];
  const float* WO    = (const float*)d_in[9];
  float* out = (float*)d_out;

  const int smem_bytes = SMEM_FL * 4;   // ~105 KB
  cudaFuncSetAttribute(na_kernel, cudaFuncAttributeMaxDynamicSharedMemorySize, smem_bytes);
  na_kernel<<<4000, 256, smem_bytes>>>(hV, hEV, hKV, hKE, maskA, WQ, WK1, WK2, WV, WO, out);
}